// round 12
// baseline (speedup 1.0000x reference)
#include <cuda_runtime.h>
#include <cuda_fp16.h>
#include <cstdint>

// Problem dims (fixed)
#define T_TOK 2048
#define D_DIM 1024
#define H_DIM 4096
#define E_NUM 8
#define K2    (E_NUM * H_DIM)   // 32768

// GEMM2 split-K: 8 expert-aligned chunks of 4096; 128 tiles x 8 = 1024 CTAs
#define KSPLIT2 8
#define KCHUNK  4096            // 64 * 64  (= one expert's H)

// GEMM tiling: CTA 128x128, warp 64x32 (2x4), BK=64, 3-stage ring, 2 CTAs/SM
#define BM 128
#define BN 128
#define BK 64
#define PADA 8    // A row = 72 halfs (144B)
#define PADB 8    // B row = 136 halfs (272B)
#define NSTAGE 3

#define A_STAGE_HALFS (BM * (BK + PADA))               // 9216
#define B_STAGE_HALFS (BK * (BN + PADB))               // 8704
#define STAGE_HALFS   (A_STAGE_HALFS + B_STAGE_HALFS)  // 17920
#define SMEM_BYTES    (NSTAGE * STAGE_HALFS * 2)       // 107,520

#define NW1 (E_NUM * D_DIM * H_DIM)   // 33,554,432
#define NX  (T_TOK * D_DIM)           // 2,097,152

// combined grid: per expert group: 512 gemm1 CTAs then 128 gemm2 CTAs
#define GROUP_CTAS 640
#define TOTAL_CTAS (E_NUM * GROUP_CTAS)   // 5120

// ---------------- scratch (static device arrays; no allocation) ----------------
__device__ __half g_xh [NX];
__device__ __half g_w1h[(size_t)NW1];                   // [e][k=D][n=H]
__device__ __half g_w2h[(size_t)NW1];                   // flat [K2][D]
__device__ __half g_hb [(size_t)T_TOK * K2];            // probs*gelu(fc1), [t][k2]
__device__ float  g_probs[T_TOK * E_NUM];
__device__ float  g_part[(size_t)KSPLIT2 * T_TOK * D_DIM]; // GEMM2 split-K partials
__device__ int    g_w1flag[E_NUM * 32];                 // lazy w1-tile conversion flags
__device__ int    g_cnt[E_NUM];                         // gemm1 per-expert completion counters

// ---------------- router: probs + x->fp16 + counter reset ----------------
__global__ void router_kernel(const float* __restrict__ x,
                              const float* __restrict__ rw,
                              const float* __restrict__ rb,
                              float* __restrict__ dout_probs) {
    __shared__ float srw[E_NUM][D_DIM];   // transposed [e][d]: conflict-free
    int tid = threadIdx.x;
    if (blockIdx.x == 0 && tid < E_NUM) g_cnt[tid] = 0;   // replay-safe reset
    for (int i = tid; i < D_DIM * E_NUM; i += 256) {
        int d = i >> 3, e = i & 7;
        srw[e][d] = rw[i];
    }
    __syncthreads();

    int gwarp = (blockIdx.x * blockDim.x + tid) >> 5;  // token id
    int lane  = tid & 31;
    if (gwarp >= T_TOK) return;
    const float* xr = x + (size_t)gwarp * D_DIM;
    float xv[32];
#pragma unroll
    for (int i = 0; i < 32; i++) xv[i] = xr[lane + 32 * i];

    __half* xh = g_xh + (size_t)gwarp * D_DIM;
#pragma unroll
    for (int i = 0; i < 32; i++) xh[lane + 32 * i] = __float2half(xv[i]);

    float logit[E_NUM];
#pragma unroll
    for (int e = 0; e < E_NUM; e++) {
        float s = 0.f;
#pragma unroll
        for (int i = 0; i < 32; i++) s += xv[i] * srw[e][lane + 32 * i];
#pragma unroll
        for (int o = 16; o; o >>= 1) s += __shfl_xor_sync(0xffffffffu, s, o);
        logit[e] = s + rb[e];
    }
    if (lane == 0) {
        float m = logit[0];
#pragma unroll
        for (int e = 1; e < E_NUM; e++) m = fmaxf(m, logit[e]);
        float p[E_NUM], sum = 0.f;
#pragma unroll
        for (int e = 0; e < E_NUM; e++) { p[e] = expf(logit[e] - m); sum += p[e]; }
        float inv = 1.f / sum;
#pragma unroll
        for (int e = 0; e < E_NUM; e++) {
            float v = p[e] * inv;
            g_probs[gwarp * E_NUM + e]    = v;
            dout_probs[gwarp * E_NUM + e] = v;
        }
    }
}

__device__ __forceinline__ float gelu_exact(float v) {
    return 0.5f * v * (1.0f + erff(v * 0.70710678118654752f));
}

// ---------------- combine: y = sum_z part[z] + sum_e probs*fc2_bias ----------------
__global__ void combine_kernel(const float* __restrict__ fc2b, float* __restrict__ y) {
    int i = (blockIdx.x * blockDim.x + threadIdx.x) * 4;
    int t = i / D_DIM, d = i % D_DIM;
    float4 s = make_float4(0.f, 0.f, 0.f, 0.f);
#pragma unroll
    for (int e = 0; e < E_NUM; e++) {
        float p = g_probs[t * E_NUM + e];
        float4 b = *reinterpret_cast<const float4*>(&fc2b[(size_t)e * D_DIM + d]);
        s.x += p * b.x; s.y += p * b.y; s.z += p * b.z; s.w += p * b.w;
    }
#pragma unroll
    for (int z = 0; z < KSPLIT2; z++) {
        float4 v = *reinterpret_cast<const float4*>(&g_part[(size_t)z * T_TOK * D_DIM + i]);
        s.x += v.x; s.y += v.y; s.z += v.z; s.w += v.w;
    }
    *reinterpret_cast<float4*>(&y[i]) = s;
}

// ---------------- fused dual-GEMM, one launch (mma.sync m16n8k16 f32.f16) ----------------
// id layout per expert group g (640 CTAs): [0..511] gemm1 expert g, [512..639] gemm2 split z=g.
// gemm1: h'[t, e*H+n] = probs*gelu(x@W1_e + b1_e); lazy w1 convert; w2 slice convert;
//        signals g_cnt[e] on completion.
// gemm2: waits g_cnt[z]==512, then part[z] = h'[:, expert z] @ W2[expert z].
__global__ __launch_bounds__(256, 2)
void moe_kernel(const float* __restrict__ fc1b, const float* __restrict__ w2src,
                const float* __restrict__ w1src) {
    extern __shared__ __half smem[];
    const int tid  = threadIdx.x;
    const int lane = tid & 31;
    const int warp = tid >> 5;
    const int wm = warp >> 2;   // 0..1 (64 rows)
    const int wn = warp & 3;    // 0..3 (32 cols)

    const int grp = blockIdx.x / GROUP_CTAS;       // expert / split index
    const int rid = blockIdx.x % GROUP_CTAS;
    const bool is_g1 = (rid < 512);
    const int bn = is_g1 ? (rid & 31) : ((rid - 512) & 7);
    const int bm = is_g1 ? (rid >> 5) : ((rid - 512) >> 3);

    const __half* A;
    const __half* B;
    size_t lda, ldb;
    int kIters;
    if (is_g1) {
        A = g_xh + (size_t)bm * BM * D_DIM;                  lda = D_DIM;
        B = g_w1h + (size_t)grp * D_DIM * H_DIM + bn * BN;   ldb = H_DIM;
        kIters = D_DIM / BK;                   // 16
    } else {
        const size_t kOff = (size_t)grp * KCHUNK;
        A = g_hb  + (size_t)bm * BM * K2 + kOff;             lda = K2;
        B = g_w2h + kOff * D_DIM + bn * BN;                  ldb = D_DIM;
        kIters = KCHUNK / BK;                  // 64
    }

    if (is_g1) {
        // lazy w1 conversion: bm==0 converts this (bn,e) B tile; others wait.
        const int fidx = bn + 32 * grp;
        if (bm == 0) {
            const float* src = w1src + (size_t)grp * D_DIM * H_DIM + bn * BN;
            __half*      dst = g_w1h + (size_t)grp * D_DIM * H_DIM + bn * BN;
            const int c = (tid & 31) * 4;           // 0..124 (float4 col)
            for (int r = tid >> 5; r < D_DIM; r += 8) {
                float4 v = *reinterpret_cast<const float4*>(src + (size_t)r * H_DIM + c);
                *reinterpret_cast<__half2*>(dst + (size_t)r * H_DIM + c)     = __floats2half2_rn(v.x, v.y);
                *reinterpret_cast<__half2*>(dst + (size_t)r * H_DIM + c + 2) = __floats2half2_rn(v.z, v.w);
            }
            __threadfence();
            __syncthreads();
            if (tid == 0) atomicExch(&g_w1flag[fidx], 1);
        } else {
            if (tid == 0) {
                while (atomicAdd(&g_w1flag[fidx], 0) == 0) { }
            }
            __threadfence();
            __syncthreads();
        }
    } else {
        // wait for gemm1 expert grp (and its w2 slice conversion) to complete
        if (tid == 0) {
            while (atomicAdd(&g_cnt[grp], 0) < 512) __nanosleep(200);
        }
        __syncthreads();
        __threadfence();
    }

    auto load_stage = [&](int s, int kt) {
        const int k0 = kt * BK;
        __half* As = smem + s * STAGE_HALFS;
        __half* Bs = As + A_STAGE_HALFS;
        // A: 128x64 halfs = 1024 x 16B chunks (8 per row)
#pragma unroll
        for (int i = 0; i < 4; i++) {
            int c = tid + i * 256;
            int row = c >> 3, off = (c & 7) * 8;
            const __half* gp = A + (size_t)row * lda + k0 + off;
            unsigned sp = (unsigned)__cvta_generic_to_shared(As + row * (BK + PADA) + off);
            asm volatile("cp.async.cg.shared.global [%0], [%1], 16;" :: "r"(sp), "l"(gp));
        }
        // B: 64x128 halfs = 1024 x 16B chunks (16 per row)
#pragma unroll
        for (int i = 0; i < 4; i++) {
            int c = tid + i * 256;
            int row = c >> 4, off = (c & 15) * 8;
            const __half* gp = B + (size_t)(k0 + row) * ldb + off;
            unsigned sp = (unsigned)__cvta_generic_to_shared(Bs + row * (BN + PADB) + off);
            asm volatile("cp.async.cg.shared.global [%0], [%1], 16;" :: "r"(sp), "l"(gp));
        }
        asm volatile("cp.async.commit_group;" ::);
    };

    float acc[4][4][4];
#pragma unroll
    for (int mf = 0; mf < 4; mf++)
#pragma unroll
        for (int nf = 0; nf < 4; nf++)
#pragma unroll
            for (int i = 0; i < 4; i++) acc[mf][nf][i] = 0.f;

    // prologue: stages 0..1
#pragma unroll
    for (int j = 0; j < NSTAGE - 1; j++) load_stage(j, j);

    if (is_g1) {
        // fused w2 fp32->fp16: this CTA's 8192-element slice.
        // cid = bn + 32*bm + 512*e -> expert e covers exactly w2 rows of expert e.
        const int cid = bn + 32 * bm + 512 * grp;   // 0..4095
        const size_t base = (size_t)cid * 8192;
#pragma unroll
        for (int t = 0; t < 8; t++) {
            size_t i = base + (size_t)(tid + t * 256) * 4;
            float4 v = *reinterpret_cast<const float4*>(w2src + i);
            __half2 h0 = __floats2half2_rn(v.x, v.y);
            __half2 h1 = __floats2half2_rn(v.z, v.w);
            *reinterpret_cast<__half2*>(&g_w2h[i])     = h0;
            *reinterpret_cast<__half2*>(&g_w2h[i + 2]) = h1;
        }
    }

    for (int j = 0; j < kIters; j++) {
        asm volatile("cp.async.wait_group 1;" ::);
        __syncthreads();   // stage j%3 visible; all warps done reading (j-1)%3

        const int p = j + NSTAGE - 1;          // prefetch into stage (j-1)%3
        if (p < kIters) load_stage(p % NSTAGE, p);
        else asm volatile("cp.async.commit_group;" ::);  // keep group count aligned

        const __half* As = smem + (j % NSTAGE) * STAGE_HALFS;
        const __half* Bs = As + A_STAGE_HALFS;

#pragma unroll
        for (int ks = 0; ks < 4; ks++) {
            const int kb = ks * 16;
            unsigned a[4][4];
            unsigned b[4][2];
#pragma unroll
            for (int mf = 0; mf < 4; mf++) {
                int mrow = wm * 64 + mf * 16 + (lane & 15);
                unsigned addr = (unsigned)__cvta_generic_to_shared(
                    As + mrow * (BK + PADA) + kb + (lane >> 4) * 8);
                asm volatile("ldmatrix.sync.aligned.m8n8.x4.shared.b16 {%0,%1,%2,%3}, [%4];"
                             : "=r"(a[mf][0]), "=r"(a[mf][1]), "=r"(a[mf][2]), "=r"(a[mf][3])
                             : "r"(addr));
            }
#pragma unroll
            for (int nf2 = 0; nf2 < 2; nf2++) {
                int ncol = wn * 32 + nf2 * 16 + (lane >> 4) * 8;
                unsigned r0, r1, r2, r3;
                unsigned addr = (unsigned)__cvta_generic_to_shared(
                    Bs + (kb + (lane & 15)) * (BN + PADB) + ncol);
                asm volatile("ldmatrix.sync.aligned.m8n8.x4.trans.shared.b16 {%0,%1,%2,%3}, [%4];"
                             : "=r"(r0), "=r"(r1), "=r"(r2), "=r"(r3)
                             : "r"(addr));
                b[nf2 * 2][0]     = r0; b[nf2 * 2][1]     = r1;
                b[nf2 * 2 + 1][0] = r2; b[nf2 * 2 + 1][1] = r3;
            }
#pragma unroll
            for (int mf = 0; mf < 4; mf++)
#pragma unroll
                for (int nf = 0; nf < 4; nf++) {
                    asm volatile(
                        "mma.sync.aligned.m16n8k16.row.col.f32.f16.f16.f32 "
                        "{%0,%1,%2,%3}, {%4,%5,%6,%7}, {%8,%9}, {%0,%1,%2,%3};"
                        : "+f"(acc[mf][nf][0]), "+f"(acc[mf][nf][1]),
                          "+f"(acc[mf][nf][2]), "+f"(acc[mf][nf][3])
                        : "r"(a[mf][0]), "r"(a[mf][1]), "r"(a[mf][2]), "r"(a[mf][3]),
                          "r"(b[nf][0]), "r"(b[nf][1]));
                }
        }
        // no bottom sync: next iter's top sync orders stage reuse
    }

    // ---------------- epilogue ----------------
    const int mBase = bm * BM + wm * 64;
    const int nBase = bn * BN + wn * 32;
    if (is_g1) {
        const int e = grp;
#pragma unroll
        for (int mf = 0; mf < 4; mf++) {
            int r0 = mBase + mf * 16 + (lane >> 2);
#pragma unroll
            for (int nf = 0; nf < 4; nf++) {
                int c0 = nBase + nf * 8 + (lane & 3) * 2;
                float bb0 = fc1b[(size_t)e * H_DIM + c0];
                float bb1 = fc1b[(size_t)e * H_DIM + c0 + 1];
#pragma unroll
                for (int h = 0; h < 2; h++) {
                    int r = r0 + h * 8;
                    float p = g_probs[r * E_NUM + e];
                    float v0 = gelu_exact(acc[mf][nf][h * 2 + 0] + bb0) * p;
                    float v1 = gelu_exact(acc[mf][nf][h * 2 + 1] + bb1) * p;
                    *reinterpret_cast<__half2*>(
                        &g_hb[(size_t)r * K2 + (size_t)e * H_DIM + c0]) =
                        __floats2half2_rn(v0, v1);
                }
            }
        }
        // signal completion of this expert tile
        __threadfence();
        __syncthreads();
        if (tid == 0) atomicAdd(&g_cnt[e], 1);
    } else {
        float* part = g_part + (size_t)grp * T_TOK * D_DIM;
#pragma unroll
        for (int mf = 0; mf < 4; mf++) {
            int r0 = mBase + mf * 16 + (lane >> 2);
#pragma unroll
            for (int nf = 0; nf < 4; nf++) {
                int c0 = nBase + nf * 8 + (lane & 3) * 2;
                *reinterpret_cast<float2*>(&part[(size_t)r0 * D_DIM + c0]) =
                    make_float2(acc[mf][nf][0], acc[mf][nf][1]);
                *reinterpret_cast<float2*>(&part[(size_t)(r0 + 8) * D_DIM + c0]) =
                    make_float2(acc[mf][nf][2], acc[mf][nf][3]);
            }
        }
    }
}

// ---------------- launch ----------------
extern "C" void kernel_launch(void* const* d_in, const int* in_sizes, int n_in,
                              void* d_out, int out_size) {
    const float* x   = (const float*)d_in[0];
    const float* rw  = (const float*)d_in[1];
    const float* rb  = (const float*)d_in[2];
    const float* w1  = (const float*)d_in[3];
    const float* b1  = (const float*)d_in[4];
    const float* w2  = (const float*)d_in[5];
    const float* b2  = (const float*)d_in[6];

    float* y      = (float*)d_out;                 // [T, D]
    float* dprobs = y + (size_t)T_TOK * D_DIM;     // [T, E]

    cudaFuncSetAttribute(moe_kernel, cudaFuncAttributeMaxDynamicSharedMemorySize, SMEM_BYTES);

    router_kernel<<<T_TOK / 8, 256>>>(x, rw, rb, dprobs);   // probs + x->fp16 + cnt reset

    moe_kernel<<<TOTAL_CTAS, 256, SMEM_BYTES>>>(b1, w2, w1); // fused gemm1+gemm2

    combine_kernel<<<(T_TOK * D_DIM) / 4 / 256, 256>>>(b2, y);
}

// round 13
// speedup vs baseline: 1.1272x; 1.1272x over previous
#include <cuda_runtime.h>
#include <cuda_fp16.h>
#include <cstdint>

// Problem dims (fixed)
#define T_TOK 2048
#define D_DIM 1024
#define H_DIM 4096
#define E_NUM 8
#define K2    (E_NUM * H_DIM)   // 32768

// GEMM2 split-K: 8 expert-aligned chunks of 4096; 128 tiles x 8 = 1024 CTAs
#define KSPLIT2 8
#define KCHUNK  4096            // = one expert's H

// GEMM tiling: CTA 128x128, warp 64x32 (2x4), BK=64, 3-stage ring, 2 CTAs/SM
#define BM 128
#define BN 128
#define BK 64
#define PADA 8    // A row = 72 halfs (144B)
#define PADB 8    // B row = 136 halfs (272B)
#define NSTAGE 3

#define A_STAGE_HALFS (BM * (BK + PADA))               // 9216
#define B_STAGE_HALFS (BK * (BN + PADB))               // 8704
#define STAGE_HALFS   (A_STAGE_HALFS + B_STAGE_HALFS)  // 17920
#define SMEM_BYTES    (NSTAGE * STAGE_HALFS * 2)       // 107,520

#define NW1 (E_NUM * D_DIM * H_DIM)   // 33,554,432
#define NX  (T_TOK * D_DIM)           // 2,097,152

#define TOTAL_CTAS (E_NUM * 512 + KSPLIT2 * 128)   // 5120

// ---------------- scratch (static device arrays; no allocation) ----------------
__device__ __half g_xh [NX];
__device__ __half g_w1h[(size_t)NW1];                   // [e][k=D][n=H]
__device__ __half g_w2h[(size_t)NW1];                   // flat [K2][D]
__device__ __half g_hb [(size_t)T_TOK * K2];            // probs*gelu(fc1), [t][k2]
__device__ float  g_probs[T_TOK * E_NUM];
__device__ float  g_part[(size_t)KSPLIT2 * T_TOK * D_DIM]; // GEMM2 split-K partials
__device__ int    g_w1flag[E_NUM * 32];                 // lazy w1-tile conversion flags
__device__ int    g_cnt[E_NUM];                         // gemm1 per-expert completion counters

// interleaved segment schedule: consumer (g2-z) dispatched one full g1 group
// after its producer (g1-z) -> no slot-spin; deadlock-free (g2-z after g1-z).
__device__ const int c_seg_type[16] = {0,0,1,0,1,0,1,0,1,0,1,0,1,0,1,1};
__device__ const int c_seg_grp [16] = {0,1,0,2,1,3,2,4,3,5,4,6,5,7,6,7};

// ---------------- router: probs + x->fp16 + counter reset ----------------
__global__ void router_kernel(const float* __restrict__ x,
                              const float* __restrict__ rw,
                              const float* __restrict__ rb,
                              float* __restrict__ dout_probs) {
    __shared__ float srw[E_NUM][D_DIM];   // transposed [e][d]: conflict-free
    int tid = threadIdx.x;
    if (blockIdx.x == 0 && tid < E_NUM) g_cnt[tid] = 0;   // replay-safe reset
    for (int i = tid; i < D_DIM * E_NUM; i += 256) {
        int d = i >> 3, e = i & 7;
        srw[e][d] = rw[i];
    }
    __syncthreads();

    int gwarp = (blockIdx.x * blockDim.x + tid) >> 5;  // token id
    int lane  = tid & 31;
    if (gwarp >= T_TOK) return;
    const float* xr = x + (size_t)gwarp * D_DIM;
    float xv[32];
#pragma unroll
    for (int i = 0; i < 32; i++) xv[i] = xr[lane + 32 * i];

    __half* xh = g_xh + (size_t)gwarp * D_DIM;
#pragma unroll
    for (int i = 0; i < 32; i++) xh[lane + 32 * i] = __float2half(xv[i]);

    float logit[E_NUM];
#pragma unroll
    for (int e = 0; e < E_NUM; e++) {
        float s = 0.f;
#pragma unroll
        for (int i = 0; i < 32; i++) s += xv[i] * srw[e][lane + 32 * i];
#pragma unroll
        for (int o = 16; o; o >>= 1) s += __shfl_xor_sync(0xffffffffu, s, o);
        logit[e] = s + rb[e];
    }
    if (lane == 0) {
        float m = logit[0];
#pragma unroll
        for (int e = 1; e < E_NUM; e++) m = fmaxf(m, logit[e]);
        float p[E_NUM], sum = 0.f;
#pragma unroll
        for (int e = 0; e < E_NUM; e++) { p[e] = expf(logit[e] - m); sum += p[e]; }
        float inv = 1.f / sum;
#pragma unroll
        for (int e = 0; e < E_NUM; e++) {
            float v = p[e] * inv;
            g_probs[gwarp * E_NUM + e]    = v;
            dout_probs[gwarp * E_NUM + e] = v;
        }
    }
}

__device__ __forceinline__ float gelu_exact(float v) {
    return 0.5f * v * (1.0f + erff(v * 0.70710678118654752f));
}

// ---------------- combine: y = sum_z part[z] + sum_e probs*fc2_bias ----------------
__global__ void combine_kernel(const float* __restrict__ fc2b, float* __restrict__ y) {
    int i = (blockIdx.x * blockDim.x + threadIdx.x) * 4;
    int t = i / D_DIM, d = i % D_DIM;
    float4 s = make_float4(0.f, 0.f, 0.f, 0.f);
#pragma unroll
    for (int e = 0; e < E_NUM; e++) {
        float p = g_probs[t * E_NUM + e];
        float4 b = *reinterpret_cast<const float4*>(&fc2b[(size_t)e * D_DIM + d]);
        s.x += p * b.x; s.y += p * b.y; s.z += p * b.z; s.w += p * b.w;
    }
#pragma unroll
    for (int z = 0; z < KSPLIT2; z++) {
        float4 v = *reinterpret_cast<const float4*>(&g_part[(size_t)z * T_TOK * D_DIM + i]);
        s.x += v.x; s.y += v.y; s.z += v.z; s.w += v.w;
    }
    *reinterpret_cast<float4*>(&y[i]) = s;
}

// ---------------- fused dual-GEMM, one launch (mma.sync m16n8k16 f32.f16) ----------------
// gemm1 (type 0): h'[t, e*H+n] = probs*gelu(x@W1_e + b1_e); lazy w1 convert;
//                 w2 slice convert; signals g_cnt[e].
// gemm2 (type 1): waits g_cnt[z]==512, part[z] = h'[:, expert z] @ W2[expert z].
__global__ __launch_bounds__(256, 2)
void moe_kernel(const float* __restrict__ fc1b, const float* __restrict__ w2src,
                const float* __restrict__ w1src) {
    extern __shared__ __half smem[];
    const int tid  = threadIdx.x;
    const int lane = tid & 31;
    const int warp = tid >> 5;
    const int wm = warp >> 2;   // 0..1 (64 rows)
    const int wn = warp & 3;    // 0..3 (32 cols)

    // decode interleaved schedule
    int rem = blockIdx.x;
    int s = 0;
#pragma unroll
    for (int i = 0; i < 16; i++) {
        int sz = c_seg_type[s] ? 128 : 512;
        if (rem < sz) break;
        rem -= sz; s++;
    }
    const bool is_g1 = (c_seg_type[s] == 0);
    const int grp = c_seg_grp[s];
    const int bn = is_g1 ? (rem & 31) : (rem & 7);
    const int bm = is_g1 ? (rem >> 5) : (rem >> 3);

    const __half* A;
    const __half* B;
    size_t lda, ldb;
    int kIters;
    if (is_g1) {
        A = g_xh + (size_t)bm * BM * D_DIM;                  lda = D_DIM;
        B = g_w1h + (size_t)grp * D_DIM * H_DIM + bn * BN;   ldb = H_DIM;
        kIters = D_DIM / BK;                   // 16
    } else {
        const size_t kOff = (size_t)grp * KCHUNK;
        A = g_hb  + (size_t)bm * BM * K2 + kOff;             lda = K2;
        B = g_w2h + kOff * D_DIM + bn * BN;                  ldb = D_DIM;
        kIters = KCHUNK / BK;                  // 64
    }

    if (is_g1) {
        // lazy w1 conversion: bm==0 converts this (bn,e) B tile; others wait.
        const int fidx = bn + 32 * grp;
        if (bm == 0) {
            const float* src = w1src + (size_t)grp * D_DIM * H_DIM + bn * BN;
            __half*      dst = g_w1h + (size_t)grp * D_DIM * H_DIM + bn * BN;
            const int c = (tid & 31) * 4;           // 0..124 (float4 col)
            for (int r = tid >> 5; r < D_DIM; r += 8) {
                float4 v = *reinterpret_cast<const float4*>(src + (size_t)r * H_DIM + c);
                *reinterpret_cast<__half2*>(dst + (size_t)r * H_DIM + c)     = __floats2half2_rn(v.x, v.y);
                *reinterpret_cast<__half2*>(dst + (size_t)r * H_DIM + c + 2) = __floats2half2_rn(v.z, v.w);
            }
            __threadfence();
            __syncthreads();
            if (tid == 0) atomicExch(&g_w1flag[fidx], 1);
        } else {
            if (tid == 0) {
                while (atomicAdd(&g_w1flag[fidx], 0) == 0) { }
            }
            __threadfence();
            __syncthreads();
        }
    } else {
        // wait for gemm1 expert grp (and its w2 slice conversion) to complete
        if (tid == 0) {
            while (atomicAdd(&g_cnt[grp], 0) < 512) __nanosleep(200);
        }
        __syncthreads();
        __threadfence();
    }

    auto load_stage = [&](int st, int kt) {
        const int k0 = kt * BK;
        __half* As = smem + st * STAGE_HALFS;
        __half* Bs = As + A_STAGE_HALFS;
        // A: 128x64 halfs = 1024 x 16B chunks (8 per row)
#pragma unroll
        for (int i = 0; i < 4; i++) {
            int c = tid + i * 256;
            int row = c >> 3, off = (c & 7) * 8;
            const __half* gp = A + (size_t)row * lda + k0 + off;
            unsigned sp = (unsigned)__cvta_generic_to_shared(As + row * (BK + PADA) + off);
            asm volatile("cp.async.cg.shared.global [%0], [%1], 16;" :: "r"(sp), "l"(gp));
        }
        // B: 64x128 halfs = 1024 x 16B chunks (16 per row)
#pragma unroll
        for (int i = 0; i < 4; i++) {
            int c = tid + i * 256;
            int row = c >> 4, off = (c & 15) * 8;
            const __half* gp = B + (size_t)(k0 + row) * ldb + off;
            unsigned sp = (unsigned)__cvta_generic_to_shared(Bs + row * (BN + PADB) + off);
            asm volatile("cp.async.cg.shared.global [%0], [%1], 16;" :: "r"(sp), "l"(gp));
        }
        asm volatile("cp.async.commit_group;" ::);
    };

    float acc[4][4][4];
#pragma unroll
    for (int mf = 0; mf < 4; mf++)
#pragma unroll
        for (int nf = 0; nf < 4; nf++)
#pragma unroll
            for (int i = 0; i < 4; i++) acc[mf][nf][i] = 0.f;

    // prologue: stages 0..1
#pragma unroll
    for (int j = 0; j < NSTAGE - 1; j++) load_stage(j, j);

    if (is_g1) {
        // fused w2 fp32->fp16: cid = bn+32*bm+512*e -> expert e converts w2 rows of expert e.
        const int cid = bn + 32 * bm + 512 * grp;   // 0..4095
        const size_t base = (size_t)cid * 8192;
#pragma unroll
        for (int t = 0; t < 8; t++) {
            size_t i = base + (size_t)(tid + t * 256) * 4;
            float4 v = *reinterpret_cast<const float4*>(w2src + i);
            __half2 h0 = __floats2half2_rn(v.x, v.y);
            __half2 h1 = __floats2half2_rn(v.z, v.w);
            *reinterpret_cast<__half2*>(&g_w2h[i])     = h0;
            *reinterpret_cast<__half2*>(&g_w2h[i + 2]) = h1;
        }
    }

    for (int j = 0; j < kIters; j++) {
        asm volatile("cp.async.wait_group 1;" ::);
        __syncthreads();   // stage j%3 visible; all warps done reading (j-1)%3

        const int p = j + NSTAGE - 1;          // prefetch into stage (j-1)%3
        if (p < kIters) load_stage(p % NSTAGE, p);
        else asm volatile("cp.async.commit_group;" ::);  // keep group count aligned

        const __half* As = smem + (j % NSTAGE) * STAGE_HALFS;
        const __half* Bs = As + A_STAGE_HALFS;

#pragma unroll
        for (int ks = 0; ks < 4; ks++) {
            const int kb = ks * 16;
            unsigned a[4][4];
            unsigned b[4][2];
#pragma unroll
            for (int mf = 0; mf < 4; mf++) {
                int mrow = wm * 64 + mf * 16 + (lane & 15);
                unsigned addr = (unsigned)__cvta_generic_to_shared(
                    As + mrow * (BK + PADA) + kb + (lane >> 4) * 8);
                asm volatile("ldmatrix.sync.aligned.m8n8.x4.shared.b16 {%0,%1,%2,%3}, [%4];"
                             : "=r"(a[mf][0]), "=r"(a[mf][1]), "=r"(a[mf][2]), "=r"(a[mf][3])
                             : "r"(addr));
            }
#pragma unroll
            for (int nf2 = 0; nf2 < 2; nf2++) {
                int ncol = wn * 32 + nf2 * 16 + (lane >> 4) * 8;
                unsigned r0, r1, r2, r3;
                unsigned addr = (unsigned)__cvta_generic_to_shared(
                    Bs + (kb + (lane & 15)) * (BN + PADB) + ncol);
                asm volatile("ldmatrix.sync.aligned.m8n8.x4.trans.shared.b16 {%0,%1,%2,%3}, [%4];"
                             : "=r"(r0), "=r"(r1), "=r"(r2), "=r"(r3)
                             : "r"(addr));
                b[nf2 * 2][0]     = r0; b[nf2 * 2][1]     = r1;
                b[nf2 * 2 + 1][0] = r2; b[nf2 * 2 + 1][1] = r3;
            }
#pragma unroll
            for (int mf = 0; mf < 4; mf++)
#pragma unroll
                for (int nf = 0; nf < 4; nf++) {
                    asm volatile(
                        "mma.sync.aligned.m16n8k16.row.col.f32.f16.f16.f32 "
                        "{%0,%1,%2,%3}, {%4,%5,%6,%7}, {%8,%9}, {%0,%1,%2,%3};"
                        : "+f"(acc[mf][nf][0]), "+f"(acc[mf][nf][1]),
                          "+f"(acc[mf][nf][2]), "+f"(acc[mf][nf][3])
                        : "r"(a[mf][0]), "r"(a[mf][1]), "r"(a[mf][2]), "r"(a[mf][3]),
                          "r"(b[nf][0]), "r"(b[nf][1]));
                }
        }
        // no bottom sync: next iter's top sync orders stage reuse
    }

    // ---------------- epilogue ----------------
    const int mBase = bm * BM + wm * 64;
    const int nBase = bn * BN + wn * 32;
    if (is_g1) {
        const int e = grp;
#pragma unroll
        for (int mf = 0; mf < 4; mf++) {
            int r0 = mBase + mf * 16 + (lane >> 2);
#pragma unroll
            for (int nf = 0; nf < 4; nf++) {
                int c0 = nBase + nf * 8 + (lane & 3) * 2;
                float bb0 = fc1b[(size_t)e * H_DIM + c0];
                float bb1 = fc1b[(size_t)e * H_DIM + c0 + 1];
#pragma unroll
                for (int h = 0; h < 2; h++) {
                    int r = r0 + h * 8;
                    float p = g_probs[r * E_NUM + e];
                    float v0 = gelu_exact(acc[mf][nf][h * 2 + 0] + bb0) * p;
                    float v1 = gelu_exact(acc[mf][nf][h * 2 + 1] + bb1) * p;
                    *reinterpret_cast<__half2*>(
                        &g_hb[(size_t)r * K2 + (size_t)e * H_DIM + c0]) =
                        __floats2half2_rn(v0, v1);
                }
            }
        }
        // signal completion of this expert tile
        __threadfence();
        __syncthreads();
        if (tid == 0) atomicAdd(&g_cnt[e], 1);
    } else {
        float* part = g_part + (size_t)grp * T_TOK * D_DIM;
#pragma unroll
        for (int mf = 0; mf < 4; mf++) {
            int r0 = mBase + mf * 16 + (lane >> 2);
#pragma unroll
            for (int nf = 0; nf < 4; nf++) {
                int c0 = nBase + nf * 8 + (lane & 3) * 2;
                *reinterpret_cast<float2*>(&part[(size_t)r0 * D_DIM + c0]) =
                    make_float2(acc[mf][nf][0], acc[mf][nf][1]);
                *reinterpret_cast<float2*>(&part[(size_t)(r0 + 8) * D_DIM + c0]) =
                    make_float2(acc[mf][nf][2], acc[mf][nf][3]);
            }
        }
    }
}

// ---------------- launch ----------------
extern "C" void kernel_launch(void* const* d_in, const int* in_sizes, int n_in,
                              void* d_out, int out_size) {
    const float* x   = (const float*)d_in[0];
    const float* rw  = (const float*)d_in[1];
    const float* rb  = (const float*)d_in[2];
    const float* w1  = (const float*)d_in[3];
    const float* b1  = (const float*)d_in[4];
    const float* w2  = (const float*)d_in[5];
    const float* b2  = (const float*)d_in[6];

    float* y      = (float*)d_out;                 // [T, D]
    float* dprobs = y + (size_t)T_TOK * D_DIM;     // [T, E]

    cudaFuncSetAttribute(moe_kernel, cudaFuncAttributeMaxDynamicSharedMemorySize, SMEM_BYTES);

    router_kernel<<<T_TOK / 8, 256>>>(x, rw, rb, dprobs);   // probs + x->fp16 + cnt reset

    moe_kernel<<<TOTAL_CTAS, 256, SMEM_BYTES>>>(b1, w2, w1); // fused, lag-interleaved

    combine_kernel<<<(T_TOK * D_DIM) / 4 / 256, 256>>>(b2, y);
}